// round 5
// baseline (speedup 1.0000x reference)
#include <cuda_runtime.h>
#include <cuda_fp16.h>
#include <cstdint>

#define HH 56
#define WW 56
#define NPIX (4 * 56 * 56)   // 12544

// Scratch (device globals — no allocation allowed). fp16 interchange format.
__device__ __align__(16) __half g_qkv[NPIX * 384];   // [pix][3*128] (q|k|v)
__device__ __align__(16) __half g_att[NPIX * 128];   // attention output

// ---------------------------------------------------------------------------
// fp16 mma + ldmatrix helpers
// ---------------------------------------------------------------------------
__device__ __forceinline__ void mma16(float* c, const uint32_t* a, const uint32_t* b) {
    asm volatile(
        "mma.sync.aligned.m16n8k16.row.col.f32.f16.f16.f32 "
        "{%0,%1,%2,%3}, {%4,%5,%6,%7}, {%8,%9}, {%0,%1,%2,%3};"
        : "+f"(c[0]), "+f"(c[1]), "+f"(c[2]), "+f"(c[3])
        : "r"(a[0]), "r"(a[1]), "r"(a[2]), "r"(a[3]), "r"(b[0]), "r"(b[1]));
}
__device__ __forceinline__ void ldm4(uint32_t* r, uint32_t addr) {
    asm volatile("ldmatrix.sync.aligned.m8n8.x4.shared.b16 {%0,%1,%2,%3}, [%4];"
                 : "=r"(r[0]), "=r"(r[1]), "=r"(r[2]), "=r"(r[3]) : "r"(addr));
}
__device__ __forceinline__ __half2 u2h2(uint32_t u) {
    return *reinterpret_cast<__half2*>(&u);
}
__device__ __forceinline__ uint32_t h22u(__half2 h) {
    return *reinterpret_cast<uint32_t*>(&h);
}

// ---------------------------------------------------------------------------
// fp16 tensor-core GEMM with bias: C[M,N] = A[M,128] @ B[128,N] + bias[N]
// BM x 128 block tile, 256 threads (8 warps 4x2), BK=32, double buffered.
// smem: A as [row][32 halves] stride 20 words; B transposed to [n][32 halves]
// stride 20 words. Stride 20 => ldmatrix 8-lane phases hit all 32 banks.
// A: f32 (AHALF=0, converted on load) or half (AHALF=1, direct copy).
// C: half (OUTHALF=1) or float.
// ---------------------------------------------------------------------------
template <int BM, bool AHALF, bool OUTHALF>
__global__ __launch_bounds__(256)
void gemm_f16(const void* __restrict__ Av, const float* __restrict__ B,
              const float* __restrict__ bias, void* __restrict__ Cv, int N)
{
    constexpr int MT = BM / 64;          // m16 tiles per warp
    constexpr int AW = BM * 20;          // A words per stage
    constexpr int BW = 128 * 20;         // B words per stage

    extern __shared__ uint32_t smg[];
    uint32_t* sA = smg;                  // 2 stages
    uint32_t* sB = smg + 2 * AW;

    const int t = threadIdx.x, w = t >> 5, lane = t & 31;
    const int wm = w & 3, wn = w >> 2;
    const int lr = lane >> 2, lc = lane & 3;
    const int bm = blockIdx.y * BM, bn = blockIdx.x * 128;

    float acc[MT][8][4];
#pragma unroll
    for (int mt = 0; mt < MT; mt++)
#pragma unroll
        for (int nt = 0; nt < 8; nt++)
#pragma unroll
            for (int i = 0; i < 4; i++) acc[mt][nt][i] = 0.f;

    // staging registers
    float4 aF[4];      // AHALF=0
    uint4  aH[1];      // AHALF=1 (BM=64)
    float4 bF[4];

    auto ldg_stage = [&](int s) {
        if constexpr (!AHALF) {
            const float* Af = (const float*)Av;
            int row = t >> 1, seg = t & 1;
#pragma unroll
            for (int i = 0; i < 4; i++)
                aF[i] = *(const float4*)(Af + (size_t)(bm + row) * 128
                                         + s * 32 + seg * 16 + i * 4);
        } else {
            const __half* Ah = (const __half*)Av;
            int row = t >> 2, seg = t & 3;
            aH[0] = *(const uint4*)(Ah + (size_t)(bm + row) * 128
                                    + s * 32 + seg * 8);
        }
#pragma unroll
        for (int i = 0; i < 4; i++) {
            int f = t + 256 * i;
            int k = f >> 5, n4 = (f & 31) << 2;
            bF[i] = *(const float4*)(B + (size_t)(s * 32 + k) * N + bn + n4);
        }
    };

    auto sts_stage = [&](int d) {
        uint32_t* dA = sA + d * AW;
        uint32_t* dB = sB + d * BW;
        if constexpr (!AHALF) {
            int row = t >> 1, seg = t & 1;
            uint4 v0, v1;
            v0.x = h22u(__floats2half2_rn(aF[0].x, aF[0].y));
            v0.y = h22u(__floats2half2_rn(aF[0].z, aF[0].w));
            v0.z = h22u(__floats2half2_rn(aF[1].x, aF[1].y));
            v0.w = h22u(__floats2half2_rn(aF[1].z, aF[1].w));
            v1.x = h22u(__floats2half2_rn(aF[2].x, aF[2].y));
            v1.y = h22u(__floats2half2_rn(aF[2].z, aF[2].w));
            v1.z = h22u(__floats2half2_rn(aF[3].x, aF[3].y));
            v1.w = h22u(__floats2half2_rn(aF[3].z, aF[3].w));
            *(uint4*)(dA + row * 20 + seg * 8)     = v0;
            *(uint4*)(dA + row * 20 + seg * 8 + 4) = v1;
        } else {
            int row = t >> 2, seg = t & 3;
            *(uint4*)(dA + row * 20 + seg * 4) = aH[0];
        }
        // B transpose to [n][k] halves (stride 40 halves)
        __half* hB = (__half*)dB;
#pragma unroll
        for (int i = 0; i < 4; i++) {
            int f = t + 256 * i;
            int k = f >> 5, n4 = (f & 31) << 2;
            hB[(n4 + 0) * 40 + k] = __float2half_rn(bF[i].x);
            hB[(n4 + 1) * 40 + k] = __float2half_rn(bF[i].y);
            hB[(n4 + 2) * 40 + k] = __float2half_rn(bF[i].z);
            hB[(n4 + 3) * 40 + k] = __float2half_rn(bF[i].w);
        }
    };

    // per-lane ldmatrix word offsets
    const int lt = lane >> 3, rw = lane & 7;
    int aOff[MT];
#pragma unroll
    for (int mt = 0; mt < MT; mt++)
        aOff[mt] = (wm * (BM / 4) + mt * 16 + ((lt & 1) << 3) + rw) * 20
                   + ((lt >> 1) << 2);
    int bOff[4];
#pragma unroll
    for (int p = 0; p < 4; p++)
        bOff[p] = (wn * 64 + p * 16 + ((lt >> 1) << 3) + rw) * 20
                  + ((lt & 1) << 2);

    ldg_stage(0);
    sts_stage(0);
    __syncthreads();

    for (int s = 0; s < 4; s++) {
        if (s < 3) ldg_stage(s + 1);

        uint32_t aB = (uint32_t)__cvta_generic_to_shared(sA + (s & 1) * AW);
        uint32_t bB = (uint32_t)__cvta_generic_to_shared(sB + (s & 1) * BW);

#pragma unroll
        for (int kk = 0; kk < 2; kk++) {
            uint32_t af[MT][4], bf[8][2];
#pragma unroll
            for (int mt = 0; mt < MT; mt++)
                ldm4(af[mt], aB + (aOff[mt] + kk * 8) * 4);
#pragma unroll
            for (int p = 0; p < 4; p++) {
                uint32_t r4[4];
                ldm4(r4, bB + (bOff[p] + kk * 8) * 4);
                bf[2 * p][0] = r4[0]; bf[2 * p][1] = r4[1];
                bf[2 * p + 1][0] = r4[2]; bf[2 * p + 1][1] = r4[3];
            }
#pragma unroll
            for (int mt = 0; mt < MT; mt++)
#pragma unroll
                for (int nt = 0; nt < 8; nt++)
                    mma16(acc[mt][nt], af[mt], bf[nt]);
        }

        if (s < 3) sts_stage((s + 1) & 1);
        __syncthreads();
    }

    // ---- epilogue with bias ----
#pragma unroll
    for (int nt = 0; nt < 8; nt++) {
        int c = bn + wn * 64 + nt * 8 + lc * 2;
        float b0 = bias[c], b1 = bias[c + 1];
#pragma unroll
        for (int mt = 0; mt < MT; mt++) {
            int r0 = bm + wm * (BM / 4) + mt * 16 + lr;
            if constexpr (OUTHALF) {
                __half* Ch = (__half*)Cv;
                *(__half2*)(Ch + (size_t)r0 * N + c) =
                    __floats2half2_rn(acc[mt][nt][0] + b0, acc[mt][nt][1] + b1);
                *(__half2*)(Ch + (size_t)(r0 + 8) * N + c) =
                    __floats2half2_rn(acc[mt][nt][2] + b0, acc[mt][nt][3] + b1);
            } else {
                float* Cf = (float*)Cv;
                *(float2*)(Cf + (size_t)r0 * N + c) =
                    make_float2(acc[mt][nt][0] + b0, acc[mt][nt][1] + b1);
                *(float2*)(Cf + (size_t)(r0 + 8) * N + c) =
                    make_float2(acc[mt][nt][2] + b0, acc[mt][nt][3] + b1);
            }
        }
    }
}

// ---------------------------------------------------------------------------
// Neighborhood attention, fp16 K/V/Q, two-phase smem reuse.
// One block = 8x8 query tile of one (b,head); union window = 14x14.
// Per-position smem stride = 20 words (80B): j-lane bank bases
// {0,20,8,28,16,4,24,12} each covering 4 banks => all 32 banks, conflict-free.
// QK dot: HFMA2 with 4 rotating half2 accumulators (abs score err ~2e-4).
// AV: f32 accumulate.
// ---------------------------------------------------------------------------
#define PSTRW 20

__global__ __launch_bounds__(64)
void natten_kernel(const __half* __restrict__ qkv, const float* __restrict__ rpb)
{
    const int tile = blockIdx.x;             // 0..48
    const int ti = tile / 7, tj = tile % 7;
    const int h = blockIdx.y, b = blockIdx.z;
    const int i0 = ti * 8, j0 = tj * 8;
    const int r0 = min(max(i0 - 3, 0), HH - 14);
    const int c0 = min(max(j0 - 3, 0), WW - 14);

    __shared__ __align__(16) uint32_t sK[196 * PSTRW];
    __shared__ float rp[169];

    const int tid = threadIdx.x;

    for (int e = tid; e < 169; e += 64) rp[e] = rpb[h * 169 + e];

    // Load 14x14 K window (halves)
    for (int e = tid; e < 784; e += 64) {
        int pos = e >> 2, seg = e & 3;
        int r = pos / 14, c = pos - r * 14;
        const uint4* src = (const uint4*)(qkv
            + ((size_t)((b * HH + r0 + r) * WW + c0 + c)) * 384 + 128 + h * 32) + seg;
        *(uint4*)(sK + pos * PSTRW + seg * 4) = *src;
    }
    __syncthreads();

    const int qi = tid >> 3, qj = tid & 7;
    const int i = i0 + qi, j = j0 + qj;
    const int si = min(max(i - 3, 0), HH - 7);
    const int sj = min(max(j - 3, 0), WW - 7);
    const int bi = si - i + 6;
    const int bj = sj - j + 6;
    const int kr = si - r0;
    const int kc = sj - c0;
    const size_t pix = (size_t)((b * HH + i) * WW + j);

    // Load q (32 halves = 16 half2)
    uint4 qv[4];
    const uint4* qp = (const uint4*)(qkv + pix * 384 + h * 32);
#pragma unroll
    for (int d = 0; d < 4; d++) qv[d] = qp[d];
    uint32_t q2[16];
    *(uint4*)&q2[0]  = qv[0]; *(uint4*)&q2[4]  = qv[1];
    *(uint4*)&q2[8]  = qv[2]; *(uint4*)&q2[12] = qv[3];

    const float scale = 0.17677669529663687f;   // 32^-0.5
    float pr[49];
    float l = 0.f;

#pragma unroll
    for (int p = 0; p < 7; p++) {
        const uint32_t* kbase = sK + ((kr + p) * 14 + kc) * PSTRW;
        const float* bbase = rp + (bi + p) * 13 + bj;
#pragma unroll
        for (int q = 0; q < 7; q++) {
            const uint32_t* kw = kbase + q * PSTRW;
            uint4 k0 = *(const uint4*)(kw);
            uint4 k1 = *(const uint4*)(kw + 4);
            uint4 k2 = *(const uint4*)(kw + 8);
            uint4 k3 = *(const uint4*)(kw + 12);
            __half2 z = __float2half2_rn(0.f);
            __half2 a0 = z, a1 = z, a2 = z, a3 = z;
            a0 = __hfma2(u2h2(q2[0]),  u2h2(k0.x), a0);
            a1 = __hfma2(u2h2(q2[1]),  u2h2(k0.y), a1);
            a2 = __hfma2(u2h2(q2[2]),  u2h2(k0.z), a2);
            a3 = __hfma2(u2h2(q2[3]),  u2h2(k0.w), a3);
            a0 = __hfma2(u2h2(q2[4]),  u2h2(k1.x), a0);
            a1 = __hfma2(u2h2(q2[5]),  u2h2(k1.y), a1);
            a2 = __hfma2(u2h2(q2[6]),  u2h2(k1.z), a2);
            a3 = __hfma2(u2h2(q2[7]),  u2h2(k1.w), a3);
            a0 = __hfma2(u2h2(q2[8]),  u2h2(k2.x), a0);
            a1 = __hfma2(u2h2(q2[9]),  u2h2(k2.y), a1);
            a2 = __hfma2(u2h2(q2[10]), u2h2(k2.z), a2);
            a3 = __hfma2(u2h2(q2[11]), u2h2(k2.w), a3);
            a0 = __hfma2(u2h2(q2[12]), u2h2(k3.x), a0);
            a1 = __hfma2(u2h2(q2[13]), u2h2(k3.y), a1);
            a2 = __hfma2(u2h2(q2[14]), u2h2(k3.z), a2);
            a3 = __hfma2(u2h2(q2[15]), u2h2(k3.w), a3);
            __half2 s01 = __hadd2(a0, a1), s23 = __hadd2(a2, a3);
            float2 f = __half22float2(__hadd2(s01, s23));
            float s = f.x + f.y;
            float e = __expf(fmaf(s, scale, bbase[q]));
            pr[p * 7 + q] = e;
            l += e;
        }
    }
    __syncthreads();   // all K reads complete

    // Load 14x14 V window into the same smem
    for (int e = tid; e < 784; e += 64) {
        int pos = e >> 2, seg = e & 3;
        int r = pos / 14, c = pos - r * 14;
        const uint4* src = (const uint4*)(qkv
            + ((size_t)((b * HH + r0 + r) * WW + c0 + c)) * 384 + 256 + h * 32) + seg;
        *(uint4*)(sK + pos * PSTRW + seg * 4) = *src;
    }
    __syncthreads();

    float4 a4[8];
#pragma unroll
    for (int d = 0; d < 8; d++) a4[d] = make_float4(0.f, 0.f, 0.f, 0.f);

#pragma unroll
    for (int p = 0; p < 7; p++) {
        const uint32_t* vbase = sK + ((kr + p) * 14 + kc) * PSTRW;
#pragma unroll
        for (int q = 0; q < 7; q++) {
            float wt = pr[p * 7 + q];
            const uint32_t* vw = vbase + q * PSTRW;
            uint4 v0 = *(const uint4*)(vw);
            uint4 v1 = *(const uint4*)(vw + 4);
            uint4 v2 = *(const uint4*)(vw + 8);
            uint4 v3 = *(const uint4*)(vw + 12);
            uint32_t vv[16];
            *(uint4*)&vv[0] = v0; *(uint4*)&vv[4] = v1;
            *(uint4*)&vv[8] = v2; *(uint4*)&vv[12] = v3;
#pragma unroll
            for (int d = 0; d < 8; d++) {
                float2 lo = __half22float2(u2h2(vv[2 * d]));
                float2 hi = __half22float2(u2h2(vv[2 * d + 1]));
                a4[d].x = fmaf(wt, lo.x, a4[d].x);
                a4[d].y = fmaf(wt, lo.y, a4[d].y);
                a4[d].z = fmaf(wt, hi.x, a4[d].z);
                a4[d].w = fmaf(wt, hi.y, a4[d].w);
            }
        }
    }

    const float inv = __frcp_rn(l);
    uint32_t ow[16];
#pragma unroll
    for (int d = 0; d < 8; d++) {
        ow[2 * d]     = h22u(__floats2half2_rn(a4[d].x * inv, a4[d].y * inv));
        ow[2 * d + 1] = h22u(__floats2half2_rn(a4[d].z * inv, a4[d].w * inv));
    }
    uint4* op = (uint4*)(g_att + pix * 128 + h * 32);
    op[0] = *(uint4*)&ow[0];
    op[1] = *(uint4*)&ow[4];
    op[2] = *(uint4*)&ow[8];
    op[3] = *(uint4*)&ow[12];
}

// ---------------------------------------------------------------------------
// Launch
// ---------------------------------------------------------------------------
extern "C" void kernel_launch(void* const* d_in, const int* in_sizes, int n_in,
                              void* d_out, int out_size)
{
    const float* x      = (const float*)d_in[0];  // [4,56,56,128]
    const float* w_qkv  = (const float*)d_in[1];  // [128,384]
    const float* b_qkv  = (const float*)d_in[2];  // [384]
    const float* rpb    = (const float*)d_in[3];  // [4,13,13]
    const float* w_proj = (const float*)d_in[4];  // [128,128]
    const float* b_proj = (const float*)d_in[5];  // [128]
    float* out = (float*)d_out;                   // [4,56,56,128] fp32
    (void)in_sizes; (void)n_in; (void)out_size;

    __half *qkv_buf, *att_buf;
    cudaGetSymbolAddress((void**)&qkv_buf, g_qkv);
    cudaGetSymbolAddress((void**)&att_buf, g_att);

    constexpr int SM128 = (2 * 128 * 20 + 2 * 128 * 20) * 4;   // 40960 B
    constexpr int SM64  = (2 * 64 * 20 + 2 * 128 * 20) * 4;    // 30720 B

    // 1) QKV projection: [12544,128] @ [128,384] + b_qkv -> half
    gemm_f16<128, false, true><<<dim3(3, NPIX / 128), 256, SM128>>>(
        x, w_qkv, b_qkv, qkv_buf, 384);

    // 2) Neighborhood attention (half in, half out)
    natten_kernel<<<dim3(49, 4, 4), 64>>>(qkv_buf, rpb);

    // 3) Output projection: [12544,128] @ [128,128] + b_proj -> float
    gemm_f16<64, true, false><<<dim3(1, NPIX / 64), 256, SM64>>>(
        att_buf, w_proj, b_proj, out, 128);
}

// round 6
// speedup vs baseline: 1.2134x; 1.2134x over previous
#include <cuda_runtime.h>
#include <cuda_fp16.h>
#include <cstdint>

#define HH 56
#define WW 56
#define NPIX (4 * 56 * 56)   // 12544

// Scratch (device globals — no allocation allowed). fp16 interchange format.
__device__ __align__(16) __half g_qkv[NPIX * 384];   // [pix][3*128] (q|k|v)
__device__ __align__(16) __half g_att[NPIX * 128];   // attention output
__device__ __align__(16) __half g_wq[384 * 128];     // w_qkv^T  [n][k] half
__device__ __align__(16) __half g_wp[128 * 128];     // w_proj^T [n][k] half

// ---------------------------------------------------------------------------
// helpers
// ---------------------------------------------------------------------------
__device__ __forceinline__ void mma16(float* c, const uint32_t* a, const uint32_t* b) {
    asm volatile(
        "mma.sync.aligned.m16n8k16.row.col.f32.f16.f16.f32 "
        "{%0,%1,%2,%3}, {%4,%5,%6,%7}, {%8,%9}, {%0,%1,%2,%3};"
        : "+f"(c[0]), "+f"(c[1]), "+f"(c[2]), "+f"(c[3])
        : "r"(a[0]), "r"(a[1]), "r"(a[2]), "r"(a[3]), "r"(b[0]), "r"(b[1]));
}
__device__ __forceinline__ void ldm4(uint32_t* r, uint32_t addr) {
    asm volatile("ldmatrix.sync.aligned.m8n8.x4.shared.b16 {%0,%1,%2,%3}, [%4];"
                 : "=r"(r[0]), "=r"(r[1]), "=r"(r[2]), "=r"(r[3]) : "r"(addr));
}
__device__ __forceinline__ __half2 u2h2(uint32_t u) {
    return *reinterpret_cast<__half2*>(&u);
}
__device__ __forceinline__ uint32_t h22u(__half2 h) {
    return *reinterpret_cast<uint32_t*>(&h);
}

// ---------------------------------------------------------------------------
// Weight prep: transpose + f32->f16.  w[k][n] -> W^T[n][k] half.
// grid (16,4): bx<12 -> w_qkv (384 cols), bx>=12 -> w_proj (128 cols).
// ---------------------------------------------------------------------------
__global__ __launch_bounds__(256)
void prep_weights(const float* __restrict__ wqkv, const float* __restrict__ wproj)
{
    __shared__ float tile[32][33];
    const int bx = blockIdx.x, by = blockIdx.y;
    const float* src;
    __half* dst;
    int ldn, n0;
    if (bx < 12) { src = wqkv;  dst = g_wq; ldn = 384; n0 = bx * 32; }
    else         { src = wproj; dst = g_wp; ldn = 128; n0 = (bx - 12) * 32; }
    const int k0 = by * 32;
    const int t = threadIdx.x;
    const int r = t >> 3, c4 = (t & 7) << 2;

    float4 v = *(const float4*)(src + (size_t)(k0 + r) * ldn + n0 + c4);
    tile[r][c4] = v.x; tile[r][c4 + 1] = v.y;
    tile[r][c4 + 2] = v.z; tile[r][c4 + 3] = v.w;
    __syncthreads();

    __half2 h0 = __floats2half2_rn(tile[c4][r], tile[c4 + 1][r]);
    __half2 h1 = __floats2half2_rn(tile[c4 + 2][r], tile[c4 + 3][r]);
    uint2 o; o.x = h22u(h0); o.y = h22u(h1);
    *(uint2*)(dst + (size_t)(n0 + r) * 128 + k0 + c4) = o;
}

// ---------------------------------------------------------------------------
// fp16 tensor-core GEMM + bias: C[M,N] = A[M,128] @ W^T + bias
// B is PRE-TRANSPOSED half [N][128] (prep kernel) -> plain uint4 copies.
// smem rows stride 20 words; ldmatrix phases all-32-bank (validated R4).
// 256 threads, 8 warps (4x2), BK=32, double buffered.
// ---------------------------------------------------------------------------
template <int BM, int BN, bool AHALF, bool OUTHALF>
__global__ __launch_bounds__(256)
void gemm_f16(const void* __restrict__ Av, const __half* __restrict__ Bh,
              const float* __restrict__ bias, void* __restrict__ Cv, int N)
{
    static_assert(AHALF ? BM == 64 : BM == 128, "");
    constexpr int MT = BM / 64;
    constexpr int NT = BN / 16;
    constexpr int NP = BN / 32;
    constexpr int AW = BM * 20;
    constexpr int BW = BN * 20;
    constexpr int BU = (BN * 4) / 256;

    extern __shared__ uint32_t smg[];
    uint32_t* sA = smg;
    uint32_t* sB = smg + 2 * AW;

    const int t = threadIdx.x, w = t >> 5, lane = t & 31;
    const int wm = w & 3, wn = w >> 2;
    const int lr = lane >> 2, lc = lane & 3;
    const int bm = blockIdx.y * BM, bn = blockIdx.x * BN;

    float acc[MT][NT][4];
#pragma unroll
    for (int mt = 0; mt < MT; mt++)
#pragma unroll
        for (int nt = 0; nt < NT; nt++)
#pragma unroll
            for (int i = 0; i < 4; i++) acc[mt][nt][i] = 0.f;

    float4 aF[4];
    uint4 aH;
    uint4 bR[BU];

    auto ldg_stage = [&](int s) {
        if constexpr (!AHALF) {
            const float* Af = (const float*)Av;
            int row = t >> 1, seg = t & 1;
#pragma unroll
            for (int i = 0; i < 4; i++)
                aF[i] = *(const float4*)(Af + (size_t)(bm + row) * 128
                                         + s * 32 + seg * 16 + i * 4);
        } else {
            const __half* Ah = (const __half*)Av;
            int row = t >> 2, seg = t & 3;
            aH = *(const uint4*)(Ah + (size_t)(bm + row) * 128 + s * 32 + seg * 8);
        }
#pragma unroll
        for (int u = 0; u < BU; u++) {
            int f = t + 256 * u;
            int row = f >> 2, seg = f & 3;
            bR[u] = *(const uint4*)(Bh + (size_t)(bn + row) * 128 + s * 32 + seg * 8);
        }
    };

    auto sts_stage = [&](int d) {
        uint32_t* dA = sA + d * AW;
        uint32_t* dB = sB + d * BW;
        if constexpr (!AHALF) {
            int row = t >> 1, seg = t & 1;
            uint4 v0, v1;
            v0.x = h22u(__floats2half2_rn(aF[0].x, aF[0].y));
            v0.y = h22u(__floats2half2_rn(aF[0].z, aF[0].w));
            v0.z = h22u(__floats2half2_rn(aF[1].x, aF[1].y));
            v0.w = h22u(__floats2half2_rn(aF[1].z, aF[1].w));
            v1.x = h22u(__floats2half2_rn(aF[2].x, aF[2].y));
            v1.y = h22u(__floats2half2_rn(aF[2].z, aF[2].w));
            v1.z = h22u(__floats2half2_rn(aF[3].x, aF[3].y));
            v1.w = h22u(__floats2half2_rn(aF[3].z, aF[3].w));
            *(uint4*)(dA + row * 20 + seg * 8)     = v0;
            *(uint4*)(dA + row * 20 + seg * 8 + 4) = v1;
        } else {
            int row = t >> 2, seg = t & 3;
            *(uint4*)(dA + row * 20 + seg * 4) = aH;
        }
#pragma unroll
        for (int u = 0; u < BU; u++) {
            int f = t + 256 * u;
            int row = f >> 2, seg = f & 3;
            *(uint4*)(dB + row * 20 + seg * 4) = bR[u];
        }
    };

    // per-lane ldmatrix word offsets (R4-validated fragment mapping)
    const int lt = lane >> 3, rw = lane & 7;
    int aOff[MT];
#pragma unroll
    for (int mt = 0; mt < MT; mt++)
        aOff[mt] = (wm * (BM / 4) + mt * 16 + ((lt & 1) << 3) + rw) * 20
                   + ((lt >> 1) << 2);
    int bOff[NP];
#pragma unroll
    for (int p = 0; p < NP; p++)
        bOff[p] = (wn * (BN / 2) + p * 16 + ((lt >> 1) << 3) + rw) * 20
                  + ((lt & 1) << 2);

    ldg_stage(0);
    sts_stage(0);
    __syncthreads();

    for (int s = 0; s < 4; s++) {
        if (s < 3) ldg_stage(s + 1);

        uint32_t aB = (uint32_t)__cvta_generic_to_shared(sA + (s & 1) * AW);
        uint32_t bB = (uint32_t)__cvta_generic_to_shared(sB + (s & 1) * BW);

#pragma unroll
        for (int kk = 0; kk < 2; kk++) {
            uint32_t af[MT][4], bf[NT][2];
#pragma unroll
            for (int mt = 0; mt < MT; mt++)
                ldm4(af[mt], aB + (aOff[mt] + kk * 8) * 4);
#pragma unroll
            for (int p = 0; p < NP; p++) {
                uint32_t r4[4];
                ldm4(r4, bB + (bOff[p] + kk * 8) * 4);
                bf[2 * p][0] = r4[0]; bf[2 * p][1] = r4[1];
                bf[2 * p + 1][0] = r4[2]; bf[2 * p + 1][1] = r4[3];
            }
#pragma unroll
            for (int mt = 0; mt < MT; mt++)
#pragma unroll
                for (int nt = 0; nt < NT; nt++)
                    mma16(acc[mt][nt], af[mt], bf[nt]);
        }

        if (s < 3) sts_stage((s + 1) & 1);
        __syncthreads();
    }

    // epilogue with bias
#pragma unroll
    for (int nt = 0; nt < NT; nt++) {
        int c = bn + wn * (BN / 2) + nt * 8 + lc * 2;
        float b0 = bias[c], b1 = bias[c + 1];
#pragma unroll
        for (int mt = 0; mt < MT; mt++) {
            int r0 = bm + wm * (BM / 4) + mt * 16 + lr;
            if constexpr (OUTHALF) {
                __half* Ch = (__half*)Cv;
                *(__half2*)(Ch + (size_t)r0 * N + c) =
                    __floats2half2_rn(acc[mt][nt][0] + b0, acc[mt][nt][1] + b1);
                *(__half2*)(Ch + (size_t)(r0 + 8) * N + c) =
                    __floats2half2_rn(acc[mt][nt][2] + b0, acc[mt][nt][3] + b1);
            } else {
                float* Cf = (float*)Cv;
                *(float2*)(Cf + (size_t)r0 * N + c) =
                    make_float2(acc[mt][nt][0] + b0, acc[mt][nt][1] + b1);
                *(float2*)(Cf + (size_t)(r0 + 8) * N + c) =
                    make_float2(acc[mt][nt][2] + b0, acc[mt][nt][3] + b1);
            }
        }
    }
}

// ---------------------------------------------------------------------------
// Neighborhood attention, fp16, key-split: 128 threads = 64 queries x 2.
// Thread (q, kh): kh=0 handles key rows p=0..3, kh=1 rows p=4..6 (4th
// iteration masked -> uniform control flow). Partial (expsum, out[32])
// combined via shfl_xor(1). Row stride 284 words puts the two halves'
// rows 16 banks apart -> conflict-free 8-lane LDS.128 phases.
// ---------------------------------------------------------------------------
#define PSTRW 20
#define RSTRW 284           // 14*20 + 4 pad

__global__ __launch_bounds__(128)
void natten_kernel(const __half* __restrict__ qkv, const float* __restrict__ rpb)
{
    const int tile = blockIdx.x;             // 0..48
    const int ti = tile / 7, tj = tile % 7;
    const int h = blockIdx.y, b = blockIdx.z;
    const int i0 = ti * 8, j0 = tj * 8;
    const int r0 = min(max(i0 - 3, 0), HH - 14);
    const int c0 = min(max(j0 - 3, 0), WW - 14);

    __shared__ __align__(16) uint32_t sK[14 * RSTRW];
    __shared__ float rp[169];

    const int tid = threadIdx.x;

    for (int e = tid; e < 169; e += 128) rp[e] = rpb[h * 169 + e];

    // Load 14x14 K window
    for (int e = tid; e < 784; e += 128) {
        int pos = e >> 2, seg = e & 3;
        int r = pos / 14, c = pos - r * 14;
        const uint4* src = (const uint4*)(qkv
            + ((size_t)((b * HH + r0 + r) * WW + c0 + c)) * 384 + 128 + h * 32) + seg;
        *(uint4*)(sK + r * RSTRW + c * PSTRW + seg * 4) = *src;
    }
    __syncthreads();

    const int q = tid >> 1, kh = tid & 1;
    const int qi = q >> 3, qj = q & 7;
    const int i = i0 + qi, j = j0 + qj;
    const int si = min(max(i - 3, 0), HH - 7);
    const int sj = min(max(j - 3, 0), WW - 7);
    const int bi = si - i + 6;
    const int bj = sj - j + 6;
    const int kr = si - r0;
    const int kc = sj - c0;
    const size_t pix = (size_t)((b * HH + i) * WW + j);

    // Load q (32 halves)
    uint32_t q2[16];
    {
        const uint4* qp = (const uint4*)(qkv + pix * 384 + h * 32);
        *(uint4*)&q2[0]  = qp[0]; *(uint4*)&q2[4]  = qp[1];
        *(uint4*)&q2[8]  = qp[2]; *(uint4*)&q2[12] = qp[3];
    }

    const int pbase = kh ? 4 : 0;
    const int np    = kh ? 3 : 4;
    const float scale = 0.17677669529663687f;   // 32^-0.5
    float pr[28];
    float l = 0.f;

#pragma unroll
    for (int pp = 0; pp < 4; pp++) {
        const bool valid = pp < np;
        const int p = pbase + (valid ? pp : 0);
        const float vm = valid ? 1.f : 0.f;
        const uint32_t* kbase = sK + (kr + p) * RSTRW + kc * PSTRW;
        const float* bbase = rp + (bi + p) * 13 + bj;
#pragma unroll
        for (int q7 = 0; q7 < 7; q7++) {
            const uint32_t* kw = kbase + q7 * PSTRW;
            uint4 k0 = *(const uint4*)(kw);
            uint4 k1 = *(const uint4*)(kw + 4);
            uint4 k2 = *(const uint4*)(kw + 8);
            uint4 k3 = *(const uint4*)(kw + 12);
            __half2 z = __float2half2_rn(0.f);
            __half2 a0 = z, a1 = z, a2 = z, a3 = z;
            a0 = __hfma2(u2h2(q2[0]),  u2h2(k0.x), a0);
            a1 = __hfma2(u2h2(q2[1]),  u2h2(k0.y), a1);
            a2 = __hfma2(u2h2(q2[2]),  u2h2(k0.z), a2);
            a3 = __hfma2(u2h2(q2[3]),  u2h2(k0.w), a3);
            a0 = __hfma2(u2h2(q2[4]),  u2h2(k1.x), a0);
            a1 = __hfma2(u2h2(q2[5]),  u2h2(k1.y), a1);
            a2 = __hfma2(u2h2(q2[6]),  u2h2(k1.z), a2);
            a3 = __hfma2(u2h2(q2[7]),  u2h2(k1.w), a3);
            a0 = __hfma2(u2h2(q2[8]),  u2h2(k2.x), a0);
            a1 = __hfma2(u2h2(q2[9]),  u2h2(k2.y), a1);
            a2 = __hfma2(u2h2(q2[10]), u2h2(k2.z), a2);
            a3 = __hfma2(u2h2(q2[11]), u2h2(k2.w), a3);
            a0 = __hfma2(u2h2(q2[12]), u2h2(k3.x), a0);
            a1 = __hfma2(u2h2(q2[13]), u2h2(k3.y), a1);
            a2 = __hfma2(u2h2(q2[14]), u2h2(k3.z), a2);
            a3 = __hfma2(u2h2(q2[15]), u2h2(k3.w), a3);
            __half2 s01 = __hadd2(a0, a1), s23 = __hadd2(a2, a3);
            float2 f = __half22float2(__hadd2(s01, s23));
            float s = f.x + f.y;
            float e = vm * __expf(fmaf(s, scale, bbase[q7]));
            pr[pp * 7 + q7] = e;
            l += e;
        }
    }
    __syncthreads();   // all K reads complete

    // Load 14x14 V window into the same smem
    for (int e = tid; e < 784; e += 128) {
        int pos = e >> 2, seg = e & 3;
        int r = pos / 14, c = pos - r * 14;
        const uint4* src = (const uint4*)(qkv
            + ((size_t)((b * HH + r0 + r) * WW + c0 + c)) * 384 + 256 + h * 32) + seg;
        *(uint4*)(sK + r * RSTRW + c * PSTRW + seg * 4) = *src;
    }
    __syncthreads();

    float4 a4[8];
#pragma unroll
    for (int d = 0; d < 8; d++) a4[d] = make_float4(0.f, 0.f, 0.f, 0.f);

#pragma unroll
    for (int pp = 0; pp < 4; pp++) {
        const bool valid = pp < np;
        const int p = pbase + (valid ? pp : 0);
        const uint32_t* vbase = sK + (kr + p) * RSTRW + kc * PSTRW;
#pragma unroll
        for (int q7 = 0; q7 < 7; q7++) {
            float wt = pr[pp * 7 + q7];
            const uint32_t* vw = vbase + q7 * PSTRW;
            uint4 v0 = *(const uint4*)(vw);
            uint4 v1 = *(const uint4*)(vw + 4);
            uint4 v2 = *(const uint4*)(vw + 8);
            uint4 v3 = *(const uint4*)(vw + 12);
            uint32_t vv[16];
            *(uint4*)&vv[0] = v0; *(uint4*)&vv[4] = v1;
            *(uint4*)&vv[8] = v2; *(uint4*)&vv[12] = v3;
#pragma unroll
            for (int d = 0; d < 8; d++) {
                float2 lo = __half22float2(u2h2(vv[2 * d]));
                float2 hi = __half22float2(u2h2(vv[2 * d + 1]));
                a4[d].x = fmaf(wt, lo.x, a4[d].x);
                a4[d].y = fmaf(wt, lo.y, a4[d].y);
                a4[d].z = fmaf(wt, hi.x, a4[d].z);
                a4[d].w = fmaf(wt, hi.y, a4[d].w);
            }
        }
    }

    // combine the two key-halves
    const unsigned m = 0xffffffffu;
    l += __shfl_xor_sync(m, l, 1);
#pragma unroll
    for (int d = 0; d < 8; d++) {
        a4[d].x += __shfl_xor_sync(m, a4[d].x, 1);
        a4[d].y += __shfl_xor_sync(m, a4[d].y, 1);
        a4[d].z += __shfl_xor_sync(m, a4[d].z, 1);
        a4[d].w += __shfl_xor_sync(m, a4[d].w, 1);
    }

    if (kh == 0) {
        const float inv = __frcp_rn(l);
        uint32_t ow[16];
#pragma unroll
        for (int d = 0; d < 8; d++) {
            ow[2 * d]     = h22u(__floats2half2_rn(a4[d].x * inv, a4[d].y * inv));
            ow[2 * d + 1] = h22u(__floats2half2_rn(a4[d].z * inv, a4[d].w * inv));
        }
        uint4* op = (uint4*)(g_att + pix * 128 + h * 32);
        op[0] = *(uint4*)&ow[0];
        op[1] = *(uint4*)&ow[4];
        op[2] = *(uint4*)&ow[8];
        op[3] = *(uint4*)&ow[12];
    }
}

// ---------------------------------------------------------------------------
// Launch
// ---------------------------------------------------------------------------
extern "C" void kernel_launch(void* const* d_in, const int* in_sizes, int n_in,
                              void* d_out, int out_size)
{
    const float* x      = (const float*)d_in[0];  // [4,56,56,128]
    const float* w_qkv  = (const float*)d_in[1];  // [128,384]
    const float* b_qkv  = (const float*)d_in[2];  // [384]
    const float* rpb    = (const float*)d_in[3];  // [4,13,13]
    const float* w_proj = (const float*)d_in[4];  // [128,128]
    const float* b_proj = (const float*)d_in[5];  // [128]
    float* out = (float*)d_out;                   // [4,56,56,128] fp32
    (void)in_sizes; (void)n_in; (void)out_size;

    __half *qkv_buf, *att_buf, *wq_buf, *wp_buf;
    cudaGetSymbolAddress((void**)&qkv_buf, g_qkv);
    cudaGetSymbolAddress((void**)&att_buf, g_att);
    cudaGetSymbolAddress((void**)&wq_buf, g_wq);
    cudaGetSymbolAddress((void**)&wp_buf, g_wp);

    constexpr int SMQ = (2 * 128 * 20 + 2 * 64 * 20) * 4;   // 30720 B
    constexpr int SMP = (2 * 64 * 20 + 2 * 64 * 20) * 4;    // 20480 B

    // 0) weight prep: f32 -> half, transposed to [N][K]
    prep_weights<<<dim3(16, 4), 256>>>(w_qkv, w_proj);

    // 1) QKV projection: [12544,128] @ [128,384] + b_qkv -> half
    gemm_f16<128, 64, false, true><<<dim3(6, NPIX / 128), 256, SMQ>>>(
        x, wq_buf, b_qkv, qkv_buf, 384);

    // 2) Neighborhood attention (half in, half out), key-split 2x
    natten_kernel<<<dim3(49, 4, 4), 128>>>(qkv_buf, rpb);

    // 3) Output projection: [12544,128] @ [128,128] + b_proj -> float
    gemm_f16<64, 64, true, false><<<dim3(2, NPIX / 64), 256, SMP>>>(
        att_buf, wp_buf, b_proj, out, 128);
}

// round 7
// speedup vs baseline: 1.5101x; 1.2446x over previous
#include <cuda_runtime.h>
#include <cuda_fp16.h>
#include <cstdint>

#define HH 56
#define WW 56
#define NPIX (4 * 56 * 56)   // 12544

// Scratch (device globals — no allocation allowed). fp16 interchange format.
__device__ __align__(16) __half g_qkv[NPIX * 384];   // [pix][3*128] (q|k|v)
__device__ __align__(16) __half g_att[NPIX * 128];   // attention output
__device__ __align__(16) __half g_wq[384 * 128];     // w_qkv^T  [n][k] half
__device__ __align__(16) __half g_wp[128 * 128];     // w_proj^T [n][k] half

// ---------------------------------------------------------------------------
// helpers
// ---------------------------------------------------------------------------
__device__ __forceinline__ void mma16(float* c, const uint32_t* a, const uint32_t* b) {
    asm volatile(
        "mma.sync.aligned.m16n8k16.row.col.f32.f16.f16.f32 "
        "{%0,%1,%2,%3}, {%4,%5,%6,%7}, {%8,%9}, {%0,%1,%2,%3};"
        : "+f"(c[0]), "+f"(c[1]), "+f"(c[2]), "+f"(c[3])
        : "r"(a[0]), "r"(a[1]), "r"(a[2]), "r"(a[3]), "r"(b[0]), "r"(b[1]));
}
__device__ __forceinline__ void ldm4(uint32_t* r, uint32_t addr) {
    asm volatile("ldmatrix.sync.aligned.m8n8.x4.shared.b16 {%0,%1,%2,%3}, [%4];"
                 : "=r"(r[0]), "=r"(r[1]), "=r"(r[2]), "=r"(r[3]) : "r"(addr));
}
__device__ __forceinline__ void ldm4t(uint32_t* r, uint32_t addr) {
    asm volatile("ldmatrix.sync.aligned.m8n8.x4.trans.shared.b16 {%0,%1,%2,%3}, [%4];"
                 : "=r"(r[0]), "=r"(r[1]), "=r"(r[2]), "=r"(r[3]) : "r"(addr));
}
__device__ __forceinline__ __half2 u2h2(uint32_t u) {
    return *reinterpret_cast<__half2*>(&u);
}
__device__ __forceinline__ uint32_t h22u(__half2 h) {
    return *reinterpret_cast<uint32_t*>(&h);
}

// ---------------------------------------------------------------------------
// Weight prep: transpose + f32->f16.  w[k][n] -> W^T[n][k] half.
// ---------------------------------------------------------------------------
__global__ __launch_bounds__(256)
void prep_weights(const float* __restrict__ wqkv, const float* __restrict__ wproj)
{
    __shared__ float tile[32][33];
    const int bx = blockIdx.x, by = blockIdx.y;
    const float* src;
    __half* dst;
    int ldn, n0;
    if (bx < 12) { src = wqkv;  dst = g_wq; ldn = 384; n0 = bx * 32; }
    else         { src = wproj; dst = g_wp; ldn = 128; n0 = (bx - 12) * 32; }
    const int k0 = by * 32;
    const int t = threadIdx.x;
    const int r = t >> 3, c4 = (t & 7) << 2;

    float4 v = *(const float4*)(src + (size_t)(k0 + r) * ldn + n0 + c4);
    tile[r][c4] = v.x; tile[r][c4 + 1] = v.y;
    tile[r][c4 + 2] = v.z; tile[r][c4 + 3] = v.w;
    __syncthreads();

    __half2 h0 = __floats2half2_rn(tile[c4][r], tile[c4 + 1][r]);
    __half2 h1 = __floats2half2_rn(tile[c4 + 2][r], tile[c4 + 3][r]);
    uint2 o; o.x = h22u(h0); o.y = h22u(h1);
    *(uint2*)(dst + (size_t)(n0 + r) * 128 + k0 + c4) = o;
}

// ---------------------------------------------------------------------------
// fp16 tensor-core GEMM + bias (R5-validated). B pre-transposed half [N][128].
// ---------------------------------------------------------------------------
template <int BM, int BN, bool AHALF, bool OUTHALF>
__global__ __launch_bounds__(256)
void gemm_f16(const void* __restrict__ Av, const __half* __restrict__ Bh,
              const float* __restrict__ bias, void* __restrict__ Cv, int N)
{
    static_assert(AHALF ? BM == 64 : BM == 128, "");
    constexpr int MT = BM / 64;
    constexpr int NT = BN / 16;
    constexpr int NP = BN / 32;
    constexpr int AW = BM * 20;
    constexpr int BW = BN * 20;
    constexpr int BU = (BN * 4) / 256;

    extern __shared__ uint32_t smg[];
    uint32_t* sA = smg;
    uint32_t* sB = smg + 2 * AW;

    const int t = threadIdx.x, w = t >> 5, lane = t & 31;
    const int wm = w & 3, wn = w >> 2;
    const int lr = lane >> 2, lc = lane & 3;
    const int bm = blockIdx.y * BM, bn = blockIdx.x * BN;

    float acc[MT][NT][4];
#pragma unroll
    for (int mt = 0; mt < MT; mt++)
#pragma unroll
        for (int nt = 0; nt < NT; nt++)
#pragma unroll
            for (int i = 0; i < 4; i++) acc[mt][nt][i] = 0.f;

    float4 aF[4];
    uint4 aH;
    uint4 bR[BU];

    auto ldg_stage = [&](int s) {
        if constexpr (!AHALF) {
            const float* Af = (const float*)Av;
            int row = t >> 1, seg = t & 1;
#pragma unroll
            for (int i = 0; i < 4; i++)
                aF[i] = *(const float4*)(Af + (size_t)(bm + row) * 128
                                         + s * 32 + seg * 16 + i * 4);
        } else {
            const __half* Ah = (const __half*)Av;
            int row = t >> 2, seg = t & 3;
            aH = *(const uint4*)(Ah + (size_t)(bm + row) * 128 + s * 32 + seg * 8);
        }
#pragma unroll
        for (int u = 0; u < BU; u++) {
            int f = t + 256 * u;
            int row = f >> 2, seg = f & 3;
            bR[u] = *(const uint4*)(Bh + (size_t)(bn + row) * 128 + s * 32 + seg * 8);
        }
    };

    auto sts_stage = [&](int d) {
        uint32_t* dA = sA + d * AW;
        uint32_t* dB = sB + d * BW;
        if constexpr (!AHALF) {
            int row = t >> 1, seg = t & 1;
            uint4 v0, v1;
            v0.x = h22u(__floats2half2_rn(aF[0].x, aF[0].y));
            v0.y = h22u(__floats2half2_rn(aF[0].z, aF[0].w));
            v0.z = h22u(__floats2half2_rn(aF[1].x, aF[1].y));
            v0.w = h22u(__floats2half2_rn(aF[1].z, aF[1].w));
            v1.x = h22u(__floats2half2_rn(aF[2].x, aF[2].y));
            v1.y = h22u(__floats2half2_rn(aF[2].z, aF[2].w));
            v1.z = h22u(__floats2half2_rn(aF[3].x, aF[3].y));
            v1.w = h22u(__floats2half2_rn(aF[3].z, aF[3].w));
            *(uint4*)(dA + row * 20 + seg * 8)     = v0;
            *(uint4*)(dA + row * 20 + seg * 8 + 4) = v1;
        } else {
            int row = t >> 2, seg = t & 3;
            *(uint4*)(dA + row * 20 + seg * 4) = aH;
        }
#pragma unroll
        for (int u = 0; u < BU; u++) {
            int f = t + 256 * u;
            int row = f >> 2, seg = f & 3;
            *(uint4*)(dB + row * 20 + seg * 4) = bR[u];
        }
    };

    const int lt = lane >> 3, rw = lane & 7;
    int aOff[MT];
#pragma unroll
    for (int mt = 0; mt < MT; mt++)
        aOff[mt] = (wm * (BM / 4) + mt * 16 + ((lt & 1) << 3) + rw) * 20
                   + ((lt >> 1) << 2);
    int bOff[NP];
#pragma unroll
    for (int p = 0; p < NP; p++)
        bOff[p] = (wn * (BN / 2) + p * 16 + ((lt >> 1) << 3) + rw) * 20
                  + ((lt & 1) << 2);

    ldg_stage(0);
    sts_stage(0);
    __syncthreads();

    for (int s = 0; s < 4; s++) {
        if (s < 3) ldg_stage(s + 1);

        uint32_t aB = (uint32_t)__cvta_generic_to_shared(sA + (s & 1) * AW);
        uint32_t bB = (uint32_t)__cvta_generic_to_shared(sB + (s & 1) * BW);

#pragma unroll
        for (int kk = 0; kk < 2; kk++) {
            uint32_t af[MT][4], bf[NT][2];
#pragma unroll
            for (int mt = 0; mt < MT; mt++)
                ldm4(af[mt], aB + (aOff[mt] + kk * 8) * 4);
#pragma unroll
            for (int p = 0; p < NP; p++) {
                uint32_t r4[4];
                ldm4(r4, bB + (bOff[p] + kk * 8) * 4);
                bf[2 * p][0] = r4[0]; bf[2 * p][1] = r4[1];
                bf[2 * p + 1][0] = r4[2]; bf[2 * p + 1][1] = r4[3];
            }
#pragma unroll
            for (int mt = 0; mt < MT; mt++)
#pragma unroll
                for (int nt = 0; nt < NT; nt++)
                    mma16(acc[mt][nt], af[mt], bf[nt]);
        }

        if (s < 3) sts_stage((s + 1) & 1);
        __syncthreads();
    }

#pragma unroll
    for (int nt = 0; nt < NT; nt++) {
        int c = bn + wn * (BN / 2) + nt * 8 + lc * 2;
        float b0 = bias[c], b1 = bias[c + 1];
#pragma unroll
        for (int mt = 0; mt < MT; mt++) {
            int r0 = bm + wm * (BM / 4) + mt * 16 + lr;
            if constexpr (OUTHALF) {
                __half* Ch = (__half*)Cv;
                *(__half2*)(Ch + (size_t)r0 * N + c) =
                    __floats2half2_rn(acc[mt][nt][0] + b0, acc[mt][nt][1] + b1);
                *(__half2*)(Ch + (size_t)(r0 + 8) * N + c) =
                    __floats2half2_rn(acc[mt][nt][2] + b0, acc[mt][nt][3] + b1);
            } else {
                float* Cf = (float*)Cv;
                *(float2*)(Cf + (size_t)r0 * N + c) =
                    make_float2(acc[mt][nt][0] + b0, acc[mt][nt][1] + b1);
                *(float2*)(Cf + (size_t)(r0 + 8) * N + c) =
                    make_float2(acc[mt][nt][2] + b0, acc[mt][nt][3] + b1);
            }
        }
    }
}

// ---------------------------------------------------------------------------
// Flash-style neighborhood attention on tensor cores.
// Block = 8x8 query tile of one (b,head); 128 threads = 4 warps.
// Warp w: 16 queries (rows qi = 2w, 2w+1; cols qj = 0..7).
// S[64,208] = Q[64,32] @ K^T (keys = padded 14x14 window, 208 = 13*16).
// Mask+bias+exp per accumulator element, P repacked to A-fragments,
// O = P[64,208] @ V[208,32] via ldmatrix.trans B-fragments.
// smem rows stride 20 words (conflict-free, R5-validated pattern).
// ---------------------------------------------------------------------------
#define SQ_OFF 0
#define SK_OFF (64 * 20)
#define SV_OFF (SK_OFF + 208 * 20)
#define SM_WORDS (SV_OFF + 208 * 20)

__global__ __launch_bounds__(128)
void natten_kernel(const __half* __restrict__ qkv, const float* __restrict__ rpb)
{
    __shared__ __align__(16) uint32_t sm[SM_WORDS];
    __shared__ float rp[169];

    const int tile = blockIdx.x;             // 0..48
    const int ti = tile / 7, tj = tile % 7;
    const int h = blockIdx.y, b = blockIdx.z;
    const int i0 = ti * 8, j0 = tj * 8;
    const int r0 = min(max(i0 - 3, 0), HH - 14);
    const int c0 = min(max(j0 - 3, 0), WW - 14);
    const int tid = threadIdx.x;

    for (int e = tid; e < 169; e += 128) rp[e] = rpb[h * 169 + e];

    // Q: 64 rows x 32 halves
#pragma unroll
    for (int e = tid; e < 256; e += 128) {
        int row = e >> 2, seg = e & 3;
        int qi = row >> 3, qj = row & 7;
        size_t pix = (size_t)((b * HH + i0 + qi) * WW + j0 + qj);
        *(uint4*)(sm + SQ_OFF + row * 20 + seg * 4) =
            *(const uint4*)(qkv + pix * 384 + h * 32 + seg * 8);
    }
    // K and V: 196 window rows
    for (int e = tid; e < 784; e += 128) {
        int row = e >> 2, seg = e & 3;
        int r = row / 14, c = row - r * 14;
        size_t pix = (size_t)((b * HH + r0 + r) * WW + c0 + c);
        const __half* base = qkv + pix * 384 + h * 32;
        *(uint4*)(sm + SK_OFF + row * 20 + seg * 4) = *(const uint4*)(base + 128 + seg * 8);
        *(uint4*)(sm + SV_OFF + row * 20 + seg * 4) = *(const uint4*)(base + 256 + seg * 8);
    }
    // zero-pad rows 196..207
    for (int e = tid; e < 240; e += 128) {
        sm[SK_OFF + 3920 + e] = 0;
        sm[SV_OFF + 3920 + e] = 0;
    }
    __syncthreads();

    const int w = tid >> 5, lane = tid & 31;
    const int lr = lane >> 2, lc = lane & 3;
    const int lt = lane >> 3, rw = lane & 7;

    const uint32_t base = (uint32_t)__cvta_generic_to_shared(sm);
    const uint32_t aAddr = base + SQ_OFF * 4
        + ((w * 16 + (lt & 1) * 8 + rw) * 20 + ((lt >> 1) << 2)) * 4;
    const uint32_t kAddr = base + SK_OFF * 4
        + ((((lt >> 1) << 3) + rw) * 20 + ((lt & 1) << 2)) * 4;
    const uint32_t vAddr = base + SV_OFF * 4
        + (((((lane >> 3) & 1) << 3) + (lane & 7)) * 20 + ((lane >> 4) << 2)) * 4;

    // ---- S = Q @ K^T ----
    float sacc[26][4];
#pragma unroll
    for (int t = 0; t < 26; t++)
#pragma unroll
        for (int i = 0; i < 4; i++) sacc[t][i] = 0.f;

    uint32_t af0[4], af1[4];
    ldm4(af0, aAddr);
    ldm4(af1, aAddr + 32);
#pragma unroll
    for (int t2 = 0; t2 < 13; t2++) {
        uint32_t r4[4];
        ldm4(r4, kAddr + t2 * 1280);
        mma16(sacc[2 * t2], af0, r4);
        mma16(sacc[2 * t2 + 1], af0, r4 + 2);
        ldm4(r4, kAddr + t2 * 1280 + 32);
        mma16(sacc[2 * t2], af1, r4);
        mma16(sacc[2 * t2 + 1], af1, r4 + 2);
    }

    // ---- mask + bias + exp ----
    const int i_lo = i0 + 2 * w, i_hi = i_lo + 1;
    const int j = j0 + lr;
    const int kri_lo = min(max(i_lo - 3, 0), HH - 7) - r0;
    const int kri_hi = min(max(i_hi - 3, 0), HH - 7) - r0;
    const int kcj = min(max(j - 3, 0), WW - 7) - c0;
    const int ci_lo = 6 - (i_lo - r0);
    const int ci_hi = 6 - (i_hi - r0);
    const int cj = 6 - (j - c0);
    const float scale = 0.17677669529663687f;   // 32^-0.5

    float l_lo = 0.f, l_hi = 0.f;
#pragma unroll
    for (int t = 0; t < 26; t++) {
#pragma unroll
        for (int c = 0; c < 2; c++) {
            int key = t * 8 + 2 * lc + c;
            int kr = (key * 2341) >> 15;
            int kc = key - kr * 14;
            bool vC = (unsigned)(kc - kcj) < 7u;
            int cb = kc + cj;

            bool v1 = vC && ((unsigned)(kr - kri_lo) < 7u);
            int idx1 = min(max((kr + ci_lo) * 13 + cb, 0), 168);
            float s1 = v1 ? fmaf(sacc[t][c], scale, rp[idx1]) : -60.f;
            float e1 = __expf(s1);
            sacc[t][c] = e1;
            l_lo += e1;

            bool v2 = vC && ((unsigned)(kr - kri_hi) < 7u);
            int idx2 = min(max((kr + ci_hi) * 13 + cb, 0), 168);
            float s2 = v2 ? fmaf(sacc[t][2 + c], scale, rp[idx2]) : -60.f;
            float e2 = __expf(s2);
            sacc[t][2 + c] = e2;
            l_hi += e2;
        }
    }
    const unsigned fm = 0xffffffffu;
    l_lo += __shfl_xor_sync(fm, l_lo, 1);
    l_lo += __shfl_xor_sync(fm, l_lo, 2);
    l_hi += __shfl_xor_sync(fm, l_hi, 1);
    l_hi += __shfl_xor_sync(fm, l_hi, 2);

    // ---- P fragments (C->A k16 pairing) ----
    uint32_t pa[13][4];
#pragma unroll
    for (int t2 = 0; t2 < 13; t2++) {
        pa[t2][0] = h22u(__floats2half2_rn(sacc[2 * t2][0], sacc[2 * t2][1]));
        pa[t2][1] = h22u(__floats2half2_rn(sacc[2 * t2][2], sacc[2 * t2][3]));
        pa[t2][2] = h22u(__floats2half2_rn(sacc[2 * t2 + 1][0], sacc[2 * t2 + 1][1]));
        pa[t2][3] = h22u(__floats2half2_rn(sacc[2 * t2 + 1][2], sacc[2 * t2 + 1][3]));
    }

    // ---- O = P @ V ----
    float out[4][4];
#pragma unroll
    for (int nt = 0; nt < 4; nt++)
#pragma unroll
        for (int i = 0; i < 4; i++) out[nt][i] = 0.f;

#pragma unroll
    for (int t2 = 0; t2 < 13; t2++) {
        uint32_t b0[4], b1[4];
        ldm4t(b0, vAddr + t2 * 1280);        // dims 0..15
        ldm4t(b1, vAddr + t2 * 1280 + 32);   // dims 16..31
        mma16(out[0], pa[t2], b0);
        mma16(out[1], pa[t2], b0 + 2);
        mma16(out[2], pa[t2], b1);
        mma16(out[3], pa[t2], b1 + 2);
    }

    // ---- normalize + store ----
    const float inv_lo = __frcp_rn(l_lo);
    const float inv_hi = __frcp_rn(l_hi);
    __half* o_lo = g_att + ((size_t)((b * HH + i_lo) * WW + j)) * 128 + h * 32;
    __half* o_hi = g_att + ((size_t)((b * HH + i_hi) * WW + j)) * 128 + h * 32;
#pragma unroll
    for (int nt = 0; nt < 4; nt++) {
        *(__half2*)(o_lo + nt * 8 + 2 * lc) =
            __floats2half2_rn(out[nt][0] * inv_lo, out[nt][1] * inv_lo);
        *(__half2*)(o_hi + nt * 8 + 2 * lc) =
            __floats2half2_rn(out[nt][2] * inv_hi, out[nt][3] * inv_hi);
    }
}

// ---------------------------------------------------------------------------
// Launch
// ---------------------------------------------------------------------------
extern "C" void kernel_launch(void* const* d_in, const int* in_sizes, int n_in,
                              void* d_out, int out_size)
{
    const float* x      = (const float*)d_in[0];  // [4,56,56,128]
    const float* w_qkv  = (const float*)d_in[1];  // [128,384]
    const float* b_qkv  = (const float*)d_in[2];  // [384]
    const float* rpb    = (const float*)d_in[3];  // [4,13,13]
    const float* w_proj = (const float*)d_in[4];  // [128,128]
    const float* b_proj = (const float*)d_in[5];  // [128]
    float* out = (float*)d_out;                   // [4,56,56,128] fp32
    (void)in_sizes; (void)n_in; (void)out_size;

    __half *qkv_buf, *att_buf, *wq_buf, *wp_buf;
    cudaGetSymbolAddress((void**)&qkv_buf, g_qkv);
    cudaGetSymbolAddress((void**)&att_buf, g_att);
    cudaGetSymbolAddress((void**)&wq_buf, g_wq);
    cudaGetSymbolAddress((void**)&wp_buf, g_wp);

    constexpr int SMQ = (2 * 128 * 20 + 2 * 64 * 20) * 4;   // 30720 B
    constexpr int SMP = (2 * 64 * 20 + 2 * 64 * 20) * 4;    // 20480 B

    // 0) weight prep: f32 -> half, transposed to [N][K]
    prep_weights<<<dim3(16, 4), 256>>>(w_qkv, w_proj);

    // 1) QKV projection: [12544,128] @ [128,384] + b_qkv -> half
    gemm_f16<128, 64, false, true><<<dim3(6, NPIX / 128), 256, SMQ>>>(
        x, wq_buf, b_qkv, qkv_buf, 384);

    // 2) Neighborhood attention (tensor-core flash style)
    natten_kernel<<<dim3(49, 4, 4), 128>>>(qkv_buf, rpb);

    // 3) Output projection: [12544,128] @ [128,128] + b_proj -> float
    gemm_f16<64, 64, true, false><<<dim3(2, NPIX / 64), 256, SMP>>>(
        att_buf, wp_buf, b_proj, out, 128);
}

// round 8
// speedup vs baseline: 1.6019x; 1.0608x over previous
#include <cuda_runtime.h>
#include <cuda_fp16.h>
#include <cstdint>

#define HH 56
#define WW 56
#define NPIX (4 * 56 * 56)   // 12544

// Scratch (device globals — no allocation allowed). fp16 interchange format.
__device__ __align__(16) __half g_qkv[NPIX * 384];   // [pix][3*128] (q|k|v)
__device__ __align__(16) __half g_att[NPIX * 128];   // attention output
__device__ __align__(16) __half g_wq[384 * 128];     // w_qkv^T  [n][k] half
__device__ __align__(16) __half g_wp[128 * 128];     // w_proj^T [n][k] half

// ---------------------------------------------------------------------------
// helpers
// ---------------------------------------------------------------------------
__device__ __forceinline__ void mma16(float* c, const uint32_t* a, const uint32_t* b) {
    asm volatile(
        "mma.sync.aligned.m16n8k16.row.col.f32.f16.f16.f32 "
        "{%0,%1,%2,%3}, {%4,%5,%6,%7}, {%8,%9}, {%0,%1,%2,%3};"
        : "+f"(c[0]), "+f"(c[1]), "+f"(c[2]), "+f"(c[3])
        : "r"(a[0]), "r"(a[1]), "r"(a[2]), "r"(a[3]), "r"(b[0]), "r"(b[1]));
}
__device__ __forceinline__ void ldm4(uint32_t* r, uint32_t addr) {
    asm volatile("ldmatrix.sync.aligned.m8n8.x4.shared.b16 {%0,%1,%2,%3}, [%4];"
                 : "=r"(r[0]), "=r"(r[1]), "=r"(r[2]), "=r"(r[3]) : "r"(addr));
}
__device__ __forceinline__ void ldm4t(uint32_t* r, uint32_t addr) {
    asm volatile("ldmatrix.sync.aligned.m8n8.x4.trans.shared.b16 {%0,%1,%2,%3}, [%4];"
                 : "=r"(r[0]), "=r"(r[1]), "=r"(r[2]), "=r"(r[3]) : "r"(addr));
}
__device__ __forceinline__ uint32_t h22u(__half2 h) {
    return *reinterpret_cast<uint32_t*>(&h);
}

// ---------------------------------------------------------------------------
// Weight prep: transpose + f32->f16.  w[k][n] -> W^T[n][k] half.
// ---------------------------------------------------------------------------
__global__ __launch_bounds__(256)
void prep_weights(const float* __restrict__ wqkv, const float* __restrict__ wproj)
{
    __shared__ float tile[32][33];
    const int bx = blockIdx.x, by = blockIdx.y;
    const float* src;
    __half* dst;
    int ldn, n0;
    if (bx < 12) { src = wqkv;  dst = g_wq; ldn = 384; n0 = bx * 32; }
    else         { src = wproj; dst = g_wp; ldn = 128; n0 = (bx - 12) * 32; }
    const int k0 = by * 32;
    const int t = threadIdx.x;
    const int r = t >> 3, c4 = (t & 7) << 2;

    float4 v = *(const float4*)(src + (size_t)(k0 + r) * ldn + n0 + c4);
    tile[r][c4] = v.x; tile[r][c4 + 1] = v.y;
    tile[r][c4 + 2] = v.z; tile[r][c4 + 3] = v.w;
    __syncthreads();

    __half2 h0 = __floats2half2_rn(tile[c4][r], tile[c4 + 1][r]);
    __half2 h1 = __floats2half2_rn(tile[c4 + 2][r], tile[c4 + 3][r]);
    uint2 o; o.x = h22u(h0); o.y = h22u(h1);
    *(uint2*)(dst + (size_t)(n0 + r) * 128 + k0 + c4) = o;
}

// ---------------------------------------------------------------------------
// Single-shot fp16 GEMM + bias: C[64-tile, 128-tile] = A[.,128] @ W^T + bias.
// Whole K=128 staged to smem at once (4 chunks, stride-20 layout), ONE sync,
// then a sync-free unrolled mainloop. 256 threads, 8 warps (4x2).
// ---------------------------------------------------------------------------
template <bool AHALF, bool OUTHALF>
__global__ __launch_bounds__(256, 2)
void gemm_f16(const void* __restrict__ Av, const __half* __restrict__ Bh,
              const float* __restrict__ bias, void* __restrict__ Cv, int N)
{
    constexpr int AWC = 64 * 20;       // words per A chunk
    constexpr int BWC = 128 * 20;      // words per B chunk

    extern __shared__ uint32_t smg[];
    uint32_t* sA = smg;                // 4 chunks
    uint32_t* sB = smg + 4 * AWC;

    const int t = threadIdx.x, w = t >> 5, lane = t & 31;
    const int wm = w & 3, wn = w >> 2;
    const int lr = lane >> 2, lc = lane & 3;
    const int bm = blockIdx.y * 64, bn = blockIdx.x * 128;

    // ---- stage A (64 x 128 halves) ----
    {
        const int row = t >> 2, seg = t & 3;
        uint32_t* dst = sA + row * 20 + seg * 4;
        if constexpr (!AHALF) {
            const float* Af = (const float*)Av + (size_t)(bm + row) * 128 + seg * 8;
#pragma unroll
            for (int s = 0; s < 4; s++) {
                float4 f0 = *(const float4*)(Af + s * 32);
                float4 f1 = *(const float4*)(Af + s * 32 + 4);
                uint4 v;
                v.x = h22u(__floats2half2_rn(f0.x, f0.y));
                v.y = h22u(__floats2half2_rn(f0.z, f0.w));
                v.z = h22u(__floats2half2_rn(f1.x, f1.y));
                v.w = h22u(__floats2half2_rn(f1.z, f1.w));
                *(uint4*)(dst + s * AWC) = v;
            }
        } else {
            const __half* Ah = (const __half*)Av + (size_t)(bm + row) * 128 + seg * 8;
#pragma unroll
            for (int s = 0; s < 4; s++)
                *(uint4*)(dst + s * AWC) = *(const uint4*)(Ah + s * 32);
        }
    }
    // ---- stage B (128 x 128 halves) ----
#pragma unroll
    for (int u = 0; u < 8; u++) {
        int f = t + 256 * u;
        int s = f >> 9, rem = f & 511;
        int row = rem >> 2, seg = rem & 3;
        *(uint4*)(sB + s * BWC + row * 20 + seg * 4) =
            *(const uint4*)(Bh + (size_t)(bn + row) * 128 + s * 32 + seg * 8);
    }
    __syncthreads();

    // ---- mainloop: 4 chunks x 2 kk, no syncs ----
    float acc[8][4];
#pragma unroll
    for (int nt = 0; nt < 8; nt++)
#pragma unroll
        for (int i = 0; i < 4; i++) acc[nt][i] = 0.f;

    const int lt = lane >> 3, rw = lane & 7;
    const uint32_t aBase = (uint32_t)__cvta_generic_to_shared(sA)
        + ((wm * 16 + ((lt & 1) << 3) + rw) * 20 + ((lt >> 1) << 2)) * 4;
    const uint32_t bBase = (uint32_t)__cvta_generic_to_shared(sB);
    int bOff[4];
#pragma unroll
    for (int p = 0; p < 4; p++)
        bOff[p] = ((wn * 64 + p * 16 + ((lt >> 1) << 3) + rw) * 20
                   + ((lt & 1) << 2)) * 4;

#pragma unroll
    for (int s = 0; s < 4; s++) {
#pragma unroll
        for (int kk = 0; kk < 2; kk++) {
            uint32_t af[4], bf[8][2];
            ldm4(af, aBase + (s * AWC + kk * 8) * 4);
#pragma unroll
            for (int p = 0; p < 4; p++) {
                uint32_t r4[4];
                ldm4(r4, bBase + bOff[p] + (s * BWC + kk * 8) * 4);
                bf[2 * p][0] = r4[0]; bf[2 * p][1] = r4[1];
                bf[2 * p + 1][0] = r4[2]; bf[2 * p + 1][1] = r4[3];
            }
#pragma unroll
            for (int nt = 0; nt < 8; nt++)
                mma16(acc[nt], af, bf[nt]);
        }
    }

    // ---- epilogue with bias ----
#pragma unroll
    for (int nt = 0; nt < 8; nt++) {
        int c = bn + wn * 64 + nt * 8 + lc * 2;
        float b0 = bias[c], b1 = bias[c + 1];
        int r0 = bm + wm * 16 + lr;
        if constexpr (OUTHALF) {
            __half* Ch = (__half*)Cv;
            *(__half2*)(Ch + (size_t)r0 * N + c) =
                __floats2half2_rn(acc[nt][0] + b0, acc[nt][1] + b1);
            *(__half2*)(Ch + (size_t)(r0 + 8) * N + c) =
                __floats2half2_rn(acc[nt][2] + b0, acc[nt][3] + b1);
        } else {
            float* Cf = (float*)Cv;
            *(float2*)(Cf + (size_t)r0 * N + c) =
                make_float2(acc[nt][0] + b0, acc[nt][1] + b1);
            *(float2*)(Cf + (size_t)(r0 + 8) * N + c) =
                make_float2(acc[nt][2] + b0, acc[nt][3] + b1);
        }
    }
}

// ---------------------------------------------------------------------------
// Streaming flash-style neighborhood attention (tensor cores).
// Per 16-key tile: S-mma -> mask+bias+exp -> pack P -> AV-mma immediately.
// Live registers ~60 (R6 held all 26 S-tiles: ~180). Mask math R6-validated.
// ---------------------------------------------------------------------------
#define SQ_OFF 0
#define SK_OFF (64 * 20)
#define SV_OFF (SK_OFF + 208 * 20)
#define SM_WORDS (SV_OFF + 208 * 20)

__global__ __launch_bounds__(128)
void natten_kernel(const __half* __restrict__ qkv, const float* __restrict__ rpb)
{
    __shared__ __align__(16) uint32_t sm[SM_WORDS];
    __shared__ float rp[169];

    const int tile = blockIdx.x;             // 0..48
    const int ti = tile / 7, tj = tile % 7;
    const int h = blockIdx.y, b = blockIdx.z;
    const int i0 = ti * 8, j0 = tj * 8;
    const int r0 = min(max(i0 - 3, 0), HH - 14);
    const int c0 = min(max(j0 - 3, 0), WW - 14);
    const int tid = threadIdx.x;

    for (int e = tid; e < 169; e += 128) rp[e] = rpb[h * 169 + e];

    // Q: 64 rows x 32 halves
#pragma unroll
    for (int e = tid; e < 256; e += 128) {
        int row = e >> 2, seg = e & 3;
        int qi = row >> 3, qj = row & 7;
        size_t pix = (size_t)((b * HH + i0 + qi) * WW + j0 + qj);
        *(uint4*)(sm + SQ_OFF + row * 20 + seg * 4) =
            *(const uint4*)(qkv + pix * 384 + h * 32 + seg * 8);
    }
    // K and V: 196 window rows
    for (int e = tid; e < 784; e += 128) {
        int row = e >> 2, seg = e & 3;
        int r = row / 14, c = row - r * 14;
        size_t pix = (size_t)((b * HH + r0 + r) * WW + c0 + c);
        const __half* base = qkv + pix * 384 + h * 32;
        *(uint4*)(sm + SK_OFF + row * 20 + seg * 4) = *(const uint4*)(base + 128 + seg * 8);
        *(uint4*)(sm + SV_OFF + row * 20 + seg * 4) = *(const uint4*)(base + 256 + seg * 8);
    }
    // zero-pad rows 196..207
    for (int e = tid; e < 240; e += 128) {
        sm[SK_OFF + 3920 + e] = 0;
        sm[SV_OFF + 3920 + e] = 0;
    }
    __syncthreads();

    const int w = tid >> 5, lane = tid & 31;
    const int lr = lane >> 2, lc = lane & 3;
    const int lt = lane >> 3, rw = lane & 7;

    const uint32_t base = (uint32_t)__cvta_generic_to_shared(sm);
    const uint32_t aAddr = base + SQ_OFF * 4
        + ((w * 16 + (lt & 1) * 8 + rw) * 20 + ((lt >> 1) << 2)) * 4;
    const uint32_t kAddr = base + SK_OFF * 4
        + ((((lt >> 1) << 3) + rw) * 20 + ((lt & 1) << 2)) * 4;
    const uint32_t vAddr = base + SV_OFF * 4
        + (((((lane >> 3) & 1) << 3) + (lane & 7)) * 20 + ((lane >> 4) << 2)) * 4;

    uint32_t af0[4], af1[4];
    ldm4(af0, aAddr);
    ldm4(af1, aAddr + 32);

    const int i_lo = i0 + 2 * w, i_hi = i_lo + 1;
    const int j = j0 + lr;
    const int kri_lo = min(max(i_lo - 3, 0), HH - 7) - r0;
    const int kri_hi = min(max(i_hi - 3, 0), HH - 7) - r0;
    const int kcj = min(max(j - 3, 0), WW - 7) - c0;
    const int ci_lo = 6 - (i_lo - r0);
    const int ci_hi = 6 - (i_hi - r0);
    const int cj = 6 - (j - c0);
    const float scale = 0.17677669529663687f;   // 32^-0.5

    float out[4][4];
#pragma unroll
    for (int nt = 0; nt < 4; nt++)
#pragma unroll
        for (int i = 0; i < 4; i++) out[nt][i] = 0.f;
    float l_lo = 0.f, l_hi = 0.f;

#pragma unroll
    for (int t2 = 0; t2 < 13; t2++) {
        // ---- S tile = Q @ K^T (16 keys) ----
        float sacc[2][4];
#pragma unroll
        for (int tt = 0; tt < 2; tt++)
#pragma unroll
            for (int i = 0; i < 4; i++) sacc[tt][i] = 0.f;
        {
            uint32_t r4[4];
            ldm4(r4, kAddr + t2 * 1280);
            mma16(sacc[0], af0, r4);
            mma16(sacc[1], af0, r4 + 2);
            ldm4(r4, kAddr + t2 * 1280 + 32);
            mma16(sacc[0], af1, r4);
            mma16(sacc[1], af1, r4 + 2);
        }
        // ---- mask + bias + exp ----
#pragma unroll
        for (int tt = 0; tt < 2; tt++) {
#pragma unroll
            for (int c = 0; c < 2; c++) {
                int key = (2 * t2 + tt) * 8 + 2 * lc + c;
                int kr = (key * 2341) >> 15;
                int kc = key - kr * 14;
                bool vC = (unsigned)(kc - kcj) < 7u;
                int cb = kc + cj;

                bool v1 = vC && ((unsigned)(kr - kri_lo) < 7u);
                int idx1 = min(max((kr + ci_lo) * 13 + cb, 0), 168);
                float e1 = __expf(v1 ? fmaf(sacc[tt][c], scale, rp[idx1]) : -60.f);
                sacc[tt][c] = e1;
                l_lo += e1;

                bool v2 = vC && ((unsigned)(kr - kri_hi) < 7u);
                int idx2 = min(max((kr + ci_hi) * 13 + cb, 0), 168);
                float e2 = __expf(v2 ? fmaf(sacc[tt][2 + c], scale, rp[idx2]) : -60.f);
                sacc[tt][2 + c] = e2;
                l_hi += e2;
            }
        }
        // ---- pack P fragments (C->A k16 pairing) ----
        uint32_t pa[4];
        pa[0] = h22u(__floats2half2_rn(sacc[0][0], sacc[0][1]));
        pa[1] = h22u(__floats2half2_rn(sacc[0][2], sacc[0][3]));
        pa[2] = h22u(__floats2half2_rn(sacc[1][0], sacc[1][1]));
        pa[3] = h22u(__floats2half2_rn(sacc[1][2], sacc[1][3]));

        // ---- AV accumulate ----
        uint32_t b0[4], b1[4];
        ldm4t(b0, vAddr + t2 * 1280);        // dims 0..15
        ldm4t(b1, vAddr + t2 * 1280 + 32);   // dims 16..31
        mma16(out[0], pa, b0);
        mma16(out[1], pa, b0 + 2);
        mma16(out[2], pa, b1);
        mma16(out[3], pa, b1 + 2);
    }

    const unsigned fm = 0xffffffffu;
    l_lo += __shfl_xor_sync(fm, l_lo, 1);
    l_lo += __shfl_xor_sync(fm, l_lo, 2);
    l_hi += __shfl_xor_sync(fm, l_hi, 1);
    l_hi += __shfl_xor_sync(fm, l_hi, 2);

    const float inv_lo = __frcp_rn(l_lo);
    const float inv_hi = __frcp_rn(l_hi);
    __half* o_lo = g_att + ((size_t)((b * HH + i_lo) * WW + j)) * 128 + h * 32;
    __half* o_hi = g_att + ((size_t)((b * HH + i_hi) * WW + j)) * 128 + h * 32;
#pragma unroll
    for (int nt = 0; nt < 4; nt++) {
        *(__half2*)(o_lo + nt * 8 + 2 * lc) =
            __floats2half2_rn(out[nt][0] * inv_lo, out[nt][1] * inv_lo);
        *(__half2*)(o_hi + nt * 8 + 2 * lc) =
            __floats2half2_rn(out[nt][2] * inv_hi, out[nt][3] * inv_hi);
    }
}

// ---------------------------------------------------------------------------
// Launch
// ---------------------------------------------------------------------------
extern "C" void kernel_launch(void* const* d_in, const int* in_sizes, int n_in,
                              void* d_out, int out_size)
{
    const float* x      = (const float*)d_in[0];  // [4,56,56,128]
    const float* w_qkv  = (const float*)d_in[1];  // [128,384]
    const float* b_qkv  = (const float*)d_in[2];  // [384]
    const float* rpb    = (const float*)d_in[3];  // [4,13,13]
    const float* w_proj = (const float*)d_in[4];  // [128,128]
    const float* b_proj = (const float*)d_in[5];  // [128]
    float* out = (float*)d_out;                   // [4,56,56,128] fp32
    (void)in_sizes; (void)n_in; (void)out_size;

    __half *qkv_buf, *att_buf, *wq_buf, *wp_buf;
    cudaGetSymbolAddress((void**)&qkv_buf, g_qkv);
    cudaGetSymbolAddress((void**)&att_buf, g_att);
    cudaGetSymbolAddress((void**)&wq_buf, g_wq);
    cudaGetSymbolAddress((void**)&wp_buf, g_wp);

    constexpr int SMG = (4 * 64 * 20 + 4 * 128 * 20) * 4;   // 61440 B

    cudaFuncSetAttribute(gemm_f16<false, true>,
                         cudaFuncAttributeMaxDynamicSharedMemorySize, SMG);
    cudaFuncSetAttribute(gemm_f16<true, false>,
                         cudaFuncAttributeMaxDynamicSharedMemorySize, SMG);

    // 0) weight prep: f32 -> half, transposed to [N][K]
    prep_weights<<<dim3(16, 4), 256>>>(w_qkv, w_proj);

    // 1) QKV projection: [12544,128] @ [128,384] + b_qkv -> half
    gemm_f16<false, true><<<dim3(3, NPIX / 64), 256, SMG>>>(
        x, wq_buf, b_qkv, qkv_buf, 384);

    // 2) Neighborhood attention (streaming tensor-core flash)
    natten_kernel<<<dim3(49, 4, 4), 128>>>(qkv_buf, rpb);

    // 3) Output projection: [12544,128] @ [128,128] + b_proj -> float
    gemm_f16<true, false><<<dim3(1, NPIX / 64), 256, SMG>>>(
        att_buf, wp_buf, b_proj, out, 128);
}